// round 1
// baseline (speedup 1.0000x reference)
#include <cuda_runtime.h>
#include <math.h>
#include <float.h>

#define L_SEQ 2048
#define NB 2
#define DM 1024
#define NH 16
#define DHEAD 64
#define SPAN_W 128
#define MROWS (L_SEQ * NB)          // 4096
#define HB (NH * NB)                // 32

// ---------------- static scratch (no allocations allowed) ----------------
__device__ float g_q[HB * L_SEQ * DHEAD];        // [h*B+b][l][dk]
__device__ float g_k[HB * L_SEQ * DHEAD];
__device__ float g_v[HB * L_SEQ * DHEAD];
__device__ float g_attnout[MROWS * DM];          // [l*B+b][h*dv]
__device__ float g_fc[MROWS * DM];               // FC output (pre-LN)
__device__ float g_rowm[HB * L_SEQ];             // softmax row max
__device__ float g_rowl[HB * L_SEQ];             // softmax row sum

// =========================================================================
// SGEMM: out = A(M x K) @ W(K x N) + bias.  BM=BN=128, BK=8, 256 threads,
// 8x8 per thread.  outsel: 0..2 -> head-transposed store to g_q/g_k/g_v,
// 3 -> plain store to g_fc (A is then g_attnout).
// =========================================================================
__global__ void __launch_bounds__(256, 2)
sgemm_kernel(const float* __restrict__ Ain, const float* __restrict__ W,
             const float* __restrict__ bias, int K, int N, int outsel)
{
    __shared__ float As[8][128];
    __shared__ float Bs[8][128];

    const float* A = (outsel == 3) ? g_attnout : Ain;
    float* out;
    int transhead;
    switch (outsel) {
        case 0: out = g_q;  transhead = 1; break;
        case 1: out = g_k;  transhead = 1; break;
        case 2: out = g_v;  transhead = 1; break;
        default: out = g_fc; transhead = 0; break;
    }

    const int tid = threadIdx.x;
    const int tx = tid & 15, ty = tid >> 4;
    const int m0 = blockIdx.x * 128;
    const int n0 = blockIdx.y * 128;

    float acc[8][8];
#pragma unroll
    for (int r = 0; r < 8; r++)
#pragma unroll
        for (int c = 0; c < 8; c++) acc[r][c] = 0.f;

    const int a_m  = tid >> 1;
    const int a_kq = (tid & 1) << 2;
    const int b_k  = tid >> 5;
    const int b_n  = (tid & 31) << 2;

    const float* Aptr = A + (size_t)(m0 + a_m) * K + a_kq;
    const float* Wptr = W + (size_t)b_k * N + n0 + b_n;

    float4 av = *(const float4*)(Aptr);
    float4 bv = *(const float4*)(Wptr);

    for (int k0 = 0; k0 < K; k0 += 8) {
        __syncthreads();
        As[a_kq + 0][a_m] = av.x;
        As[a_kq + 1][a_m] = av.y;
        As[a_kq + 2][a_m] = av.z;
        As[a_kq + 3][a_m] = av.w;
        *(float4*)&Bs[b_k][b_n] = bv;
        __syncthreads();
        if (k0 + 8 < K) {
            av = *(const float4*)(Aptr + k0 + 8);
            bv = *(const float4*)(Wptr + (size_t)(k0 + 8) * N);
        }
#pragma unroll
        for (int kk = 0; kk < 8; kk++) {
            float a[8], b[8];
            *(float4*)&a[0] = *(const float4*)&As[kk][ty * 8];
            *(float4*)&a[4] = *(const float4*)&As[kk][ty * 8 + 4];
            *(float4*)&b[0] = *(const float4*)&Bs[kk][tx * 8];
            *(float4*)&b[4] = *(const float4*)&Bs[kk][tx * 8 + 4];
#pragma unroll
            for (int r = 0; r < 8; r++)
#pragma unroll
                for (int c = 0; c < 8; c++)
                    acc[r][c] = fmaf(a[r], b[c], acc[r][c]);
        }
    }

    const int n_base = n0 + tx * 8;
    float bvals[8];
#pragma unroll
    for (int c = 0; c < 8; c++) bvals[c] = bias[n_base + c];

    if (!transhead) {
#pragma unroll
        for (int r = 0; r < 8; r++) {
            int m = m0 + ty * 8 + r;
            float* dst = out + (size_t)m * N + n_base;
            float4 v0 = make_float4(acc[r][0] + bvals[0], acc[r][1] + bvals[1],
                                    acc[r][2] + bvals[2], acc[r][3] + bvals[3]);
            float4 v1 = make_float4(acc[r][4] + bvals[4], acc[r][5] + bvals[5],
                                    acc[r][6] + bvals[6], acc[r][7] + bvals[7]);
            *(float4*)&dst[0] = v0;
            *(float4*)&dst[4] = v1;
        }
    } else {
        const int h = n_base >> 6;       // head (8-col group never crosses 64)
        const int dkb = n_base & 63;
#pragma unroll
        for (int r = 0; r < 8; r++) {
            int m = m0 + ty * 8 + r;
            int l = m >> 1, bb = m & 1;
            float* dst = out + ((size_t)(h * NB + bb) * L_SEQ + l) * DHEAD + dkb;
            float4 v0 = make_float4(acc[r][0] + bvals[0], acc[r][1] + bvals[1],
                                    acc[r][2] + bvals[2], acc[r][3] + bvals[3]);
            float4 v1 = make_float4(acc[r][4] + bvals[4], acc[r][5] + bvals[5],
                                    acc[r][6] + bvals[6], acc[r][7] + bvals[7]);
            *(float4*)&dst[0] = v0;
            *(float4*)&dst[4] = v1;
        }
    }
}

// =========================================================================
// Banded attention.  Block = (i-block of 128 rows) x (head*batch).
// Phase 1: raw scaled scores -> attn output region (scratch) + row max.
// Phase 2: P = exp(s - m) in smem, O += P @ V, row sums.
// =========================================================================
#define QS_STRIDE 132
#define VS_STRIDE 68
#define PS_STRIDE 129
#define QS_FLOATS (64 * QS_STRIDE)            // 8448
#define KV_FLOATS 8704                         // max(64*132, 128*68)
#define PS_FLOATS (128 * PS_STRIDE)           // 16512
#define ATTN_SMEM_BYTES ((QS_FLOATS + KV_FLOATS + PS_FLOATS) * 4)

__global__ void __launch_bounds__(256)
attn_kernel(float* __restrict__ attn_raw)
{
    extern __shared__ float smx[];
    float* Qs  = smx;
    float* KVs = smx + QS_FLOATS;
    float* Ps  = smx + QS_FLOATS + KV_FLOATS;

    const int tid = threadIdx.x;
    const int tx = tid & 15, ty = tid >> 4;
    const int i0 = blockIdx.x * 128;
    const int hb = blockIdx.y;

    const float* Qg = g_q + (size_t)hb * L_SEQ * DHEAD;
    const float* Kg = g_k + (size_t)hb * L_SEQ * DHEAD;
    const float* Vg = g_v + (size_t)hb * L_SEQ * DHEAD;
    float* rawbase = attn_raw + (size_t)hb * L_SEQ * L_SEQ;

    // load Q tile transposed: Qs[dk][i]
    {
        const float* src = Qg + (size_t)i0 * DHEAD;
        for (int idx = tid; idx < 128 * 16; idx += 256) {
            int r = idx >> 4, kq = (idx & 15) << 2;
            float4 v = *(const float4*)&src[r * 64 + kq];
            Qs[(kq + 0) * QS_STRIDE + r] = v.x;
            Qs[(kq + 1) * QS_STRIDE + r] = v.y;
            Qs[(kq + 2) * QS_STRIDE + r] = v.z;
            Qs[(kq + 3) * QS_STRIDE + r] = v.w;
        }
    }

    float rm[8];
#pragma unroll
    for (int r = 0; r < 8; r++) rm[r] = -FLT_MAX;

    const int ibase = i0 + ty * 8;

    // ---------------- Phase 1: raw scores + row max ----------------
    for (int cch = 0; cch < 3; cch++) {
        int j0 = i0 + (cch - 1) * 128;
        if (j0 < 0 || j0 >= L_SEQ) continue;
        __syncthreads();
        {
            const float* src = Kg + (size_t)j0 * DHEAD;
            for (int idx = tid; idx < 128 * 16; idx += 256) {
                int r = idx >> 4, kq = (idx & 15) << 2;
                float4 v = *(const float4*)&src[r * 64 + kq];
                KVs[(kq + 0) * QS_STRIDE + r] = v.x;
                KVs[(kq + 1) * QS_STRIDE + r] = v.y;
                KVs[(kq + 2) * QS_STRIDE + r] = v.z;
                KVs[(kq + 3) * QS_STRIDE + r] = v.w;
            }
        }
        __syncthreads();
        float s[8][8];
#pragma unroll
        for (int r = 0; r < 8; r++)
#pragma unroll
            for (int c = 0; c < 8; c++) s[r][c] = 0.f;

        for (int kk = 0; kk < 64; kk++) {
            float a[8], b[8];
            *(float4*)&a[0] = *(const float4*)&Qs[kk * QS_STRIDE + ty * 8];
            *(float4*)&a[4] = *(const float4*)&Qs[kk * QS_STRIDE + ty * 8 + 4];
            *(float4*)&b[0] = *(const float4*)&KVs[kk * QS_STRIDE + tx * 8];
            *(float4*)&b[4] = *(const float4*)&KVs[kk * QS_STRIDE + tx * 8 + 4];
#pragma unroll
            for (int r = 0; r < 8; r++)
#pragma unroll
                for (int c = 0; c < 8; c++)
                    s[r][c] = fmaf(a[r], b[c], s[r][c]);
        }
        const int jbase = j0 + tx * 8;
#pragma unroll
        for (int r = 0; r < 8; r++) {
            int i = ibase + r;
            float* rowp = rawbase + (size_t)i * L_SEQ;
#pragma unroll
            for (int c2 = 0; c2 < 8; c2++) {
                int j = jbase + c2;
                int d = i - j;
                if (d >= -SPAN_W && d <= SPAN_W) {
                    float v = s[r][c2] * 0.125f;
                    rowp[j] = v;
                    rm[r] = fmaxf(rm[r], v);
                }
            }
        }
    }

    // reduce row max across the 16 tx lanes
#pragma unroll
    for (int r = 0; r < 8; r++) {
#pragma unroll
        for (int off = 8; off > 0; off >>= 1)
            rm[r] = fmaxf(rm[r], __shfl_xor_sync(0xffffffffu, rm[r], off, 16));
    }

    // ---------------- Phase 2: P = exp(s-m), O = P @ V, row sums ---------
    float O[8][4];
    float ll[8];
#pragma unroll
    for (int r = 0; r < 8; r++) {
        ll[r] = 0.f;
#pragma unroll
        for (int c = 0; c < 4; c++) O[r][c] = 0.f;
    }

    for (int cch = 0; cch < 3; cch++) {
        int j0 = i0 + (cch - 1) * 128;
        if (j0 < 0 || j0 >= L_SEQ) continue;
        __syncthreads();
        {
            const float* src = Vg + (size_t)j0 * DHEAD;
            for (int idx = tid; idx < 128 * 16; idx += 256) {
                int r = idx >> 4, kq = (idx & 15) << 2;
                *(float4*)&KVs[r * VS_STRIDE + kq] = *(const float4*)&src[r * 64 + kq];
            }
        }
        const int jbase = j0 + tx * 8;
#pragma unroll
        for (int r = 0; r < 8; r++) {
            int i = ibase + r;
            const float* rowp = rawbase + (size_t)i * L_SEQ;
            float* prow = Ps + (size_t)(ty * 8 + r) * PS_STRIDE + tx * 8;
#pragma unroll
            for (int c2 = 0; c2 < 8; c2++) {
                int j = jbase + c2;
                int d = i - j;
                float p = 0.f;
                if (d >= -SPAN_W && d <= SPAN_W)
                    p = __expf(rowp[j] - rm[r]);
                ll[r] += p;
                prow[c2] = p;
            }
        }
        __syncthreads();
        for (int j = 0; j < 128; j++) {
            float4 v4 = *(const float4*)&KVs[j * VS_STRIDE + tx * 4];
#pragma unroll
            for (int r = 0; r < 8; r++) {
                float pv = Ps[(size_t)(ty * 8 + r) * PS_STRIDE + j];
                O[r][0] = fmaf(pv, v4.x, O[r][0]);
                O[r][1] = fmaf(pv, v4.y, O[r][1]);
                O[r][2] = fmaf(pv, v4.z, O[r][2]);
                O[r][3] = fmaf(pv, v4.w, O[r][3]);
            }
        }
    }

    // reduce row sums across tx lanes
#pragma unroll
    for (int r = 0; r < 8; r++) {
#pragma unroll
        for (int off = 8; off > 0; off >>= 1)
            ll[r] += __shfl_xor_sync(0xffffffffu, ll[r], off, 16);
    }

    const int h = hb >> 1, bb = hb & 1;
#pragma unroll
    for (int r = 0; r < 8; r++) {
        int i = ibase + r;
        float inv = 1.f / ll[r];
        float4 o4 = make_float4(O[r][0] * inv, O[r][1] * inv,
                                O[r][2] * inv, O[r][3] * inv);
        *(float4*)&g_attnout[((size_t)i * NB + bb) * DM + h * DHEAD + tx * 4] = o4;
        if (tx == 0) {
            g_rowm[hb * L_SEQ + i] = rm[r];
            g_rowl[hb * L_SEQ + i] = ll[r];
        }
    }
}

// =========================================================================
// Normalize raw scores -> softmax weights; zero everything out of band.
// One block per attention row (hb*L + i), 256 threads x 8 cols.
// =========================================================================
__global__ void __launch_bounds__(256)
attn_norm_kernel(float* __restrict__ attn)
{
    const int row = blockIdx.x;               // hb*L + i
    const int i = row & (L_SEQ - 1);
    const float m = g_rowm[row];
    const float inv = 1.f / g_rowl[row];
    float* p = attn + (size_t)row * L_SEQ;
    const int j0 = threadIdx.x * 8;
    float out[8];
#pragma unroll
    for (int u = 0; u < 8; u++) {
        int j = j0 + u;
        int d = i - j;
        out[u] = (d >= -SPAN_W && d <= SPAN_W) ? __expf(p[j] - m) * inv : 0.f;
    }
    *(float4*)&p[j0]     = make_float4(out[0], out[1], out[2], out[3]);
    *(float4*)&p[j0 + 4] = make_float4(out[4], out[5], out[6], out[7]);
}

// =========================================================================
// Residual + LayerNorm.  One block per row (m = l*B+b), 256 threads x 4.
// =========================================================================
__global__ void __launch_bounds__(256)
ln_kernel(const float* __restrict__ query, const float* __restrict__ gamma,
          const float* __restrict__ beta, float* __restrict__ y)
{
    __shared__ float red[16];
    const int row = blockIdx.x;
    const int t = threadIdx.x;

    float4 f = *(const float4*)&g_fc[(size_t)row * DM + t * 4];
    float4 q = *(const float4*)&query[(size_t)row * DM + t * 4];
    float v0 = f.x + q.x, v1 = f.y + q.y, v2 = f.z + q.z, v3 = f.w + q.w;

    float s = v0 + v1 + v2 + v3;
    float s2 = v0 * v0 + v1 * v1 + v2 * v2 + v3 * v3;
#pragma unroll
    for (int off = 16; off > 0; off >>= 1) {
        s  += __shfl_xor_sync(0xffffffffu, s, off);
        s2 += __shfl_xor_sync(0xffffffffu, s2, off);
    }
    const int warp = t >> 5, lane = t & 31;
    if (lane == 0) { red[warp] = s; red[warp + 8] = s2; }
    __syncthreads();
    if (t < 32) {
        float a  = (lane < 8) ? red[lane] : 0.f;
        float b2 = (lane < 8) ? red[lane + 8] : 0.f;
#pragma unroll
        for (int off = 4; off > 0; off >>= 1) {
            a  += __shfl_xor_sync(0xffffffffu, a, off);
            b2 += __shfl_xor_sync(0xffffffffu, b2, off);
        }
        if (lane == 0) { red[0] = a; red[1] = b2; }
    }
    __syncthreads();
    const float mean = red[0] * (1.f / DM);
    const float var  = red[1] * (1.f / DM) - mean * mean;
    const float rstd = rsqrtf(var + 1e-5f);

    float4 g  = *(const float4*)&gamma[t * 4];
    float4 be = *(const float4*)&beta[t * 4];
    float4 o;
    o.x = (v0 - mean) * rstd * g.x + be.x;
    o.y = (v1 - mean) * rstd * g.y + be.y;
    o.z = (v2 - mean) * rstd * g.z + be.z;
    o.w = (v3 - mean) * rstd * g.w + be.w;
    *(float4*)&y[(size_t)row * DM + t * 4] = o;
}

// =========================================================================
extern "C" void kernel_launch(void* const* d_in, const int* in_sizes, int n_in,
                              void* d_out, int out_size)
{
    const float* query = (const float*)d_in[0];
    const float* key   = (const float*)d_in[1];
    const float* value = (const float*)d_in[2];
    const float* Wq    = (const float*)d_in[3];
    const float* bq    = (const float*)d_in[4];
    const float* Wk    = (const float*)d_in[5];
    const float* bk    = (const float*)d_in[6];
    const float* Wv    = (const float*)d_in[7];
    const float* bv    = (const float*)d_in[8];
    const float* Wfc   = (const float*)d_in[9];
    const float* bfc   = (const float*)d_in[10];
    const float* gamma = (const float*)d_in[11];
    const float* beta  = (const float*)d_in[12];

    float* y_out = (float*)d_out;
    float* attn_out = y_out + (size_t)L_SEQ * NB * DM;

    cudaFuncSetAttribute(attn_kernel,
                         cudaFuncAttributeMaxDynamicSharedMemorySize,
                         ATTN_SMEM_BYTES);

    dim3 gproj(MROWS / 128, DM / 128);
    sgemm_kernel<<<gproj, 256>>>(query, Wq, bq, DM, NH * DHEAD, 0);
    sgemm_kernel<<<gproj, 256>>>(key,   Wk, bk, DM, NH * DHEAD, 1);
    sgemm_kernel<<<gproj, 256>>>(value, Wv, bv, DM, NH * DHEAD, 2);

    attn_kernel<<<dim3(L_SEQ / 128, HB), 256, ATTN_SMEM_BYTES>>>(attn_out);

    sgemm_kernel<<<gproj, 256>>>(nullptr, Wfc, bfc, DM, DM, 3);

    ln_kernel<<<MROWS, 256>>>(query, gamma, beta, y_out);

    attn_norm_kernel<<<HB * L_SEQ, 256>>>(attn_out);
}

// round 2
// speedup vs baseline: 1.0724x; 1.0724x over previous
#include <cuda_runtime.h>
#include <math.h>
#include <float.h>

#define L_SEQ 2048
#define NB 2
#define DM 1024
#define NH 16
#define DHEAD 64
#define SPAN_W 128
#define MROWS (L_SEQ * NB)          // 4096
#define HB (NH * NB)                // 32

// ---------------- static scratch (no allocations allowed) ----------------
__device__ float g_q[HB * L_SEQ * DHEAD];        // [h*B+b][l][dk]
__device__ float g_k[HB * L_SEQ * DHEAD];
__device__ float g_v[HB * L_SEQ * DHEAD];
__device__ float g_attnout[MROWS * DM];          // [l*B+b][h*dv]
__device__ float g_fc[MROWS * DM];               // FC output (pre-LN)
__device__ float g_rowm[HB * L_SEQ];             // softmax row max
__device__ float g_rowl[HB * L_SEQ];             // softmax row sum

// =========================================================================
// Double-buffered SGEMM core (BM=BN=128, BK=8, 256 thr, 8x8/thr).
// Computes C-tile = A(M x 1024) @ W(1024 x 128-slice) for row/col block.
// =========================================================================
__device__ __forceinline__ void gemm_tile(
    const float* __restrict__ A, const float* __restrict__ W,
    const float* __restrict__ bias, float* __restrict__ out,
    int K, int N, int m0, int n0, int transhead)
{
    __shared__ float As[2][8][128];
    __shared__ float Bs[2][8][128];

    const int tid = threadIdx.x;
    const int tx = tid & 15, ty = tid >> 4;

    float acc[8][8];
#pragma unroll
    for (int r = 0; r < 8; r++)
#pragma unroll
        for (int c = 0; c < 8; c++) acc[r][c] = 0.f;

    const int a_m  = tid >> 1;
    const int a_kq = (tid & 1) << 2;
    const int b_k  = tid >> 5;
    const int b_n  = (tid & 31) << 2;

    const float* Aptr = A + (size_t)(m0 + a_m) * K + a_kq;
    const float* Wptr = W + (size_t)b_k * N + n0 + b_n;

    float4 av = *(const float4*)(Aptr);
    float4 bv = *(const float4*)(Wptr);

    int buf = 0;
    As[0][a_kq + 0][a_m] = av.x;
    As[0][a_kq + 1][a_m] = av.y;
    As[0][a_kq + 2][a_m] = av.z;
    As[0][a_kq + 3][a_m] = av.w;
    *(float4*)&Bs[0][b_k][b_n] = bv;
    __syncthreads();

    for (int k0 = 0; k0 < K; k0 += 8) {
        const int has_next = (k0 + 8 < K);
        if (has_next) {
            av = *(const float4*)(Aptr + k0 + 8);
            bv = *(const float4*)(Wptr + (size_t)(k0 + 8) * N);
        }
#pragma unroll
        for (int kk = 0; kk < 8; kk++) {
            float a[8], b[8];
            *(float4*)&a[0] = *(const float4*)&As[buf][kk][ty * 8];
            *(float4*)&a[4] = *(const float4*)&As[buf][kk][ty * 8 + 4];
            *(float4*)&b[0] = *(const float4*)&Bs[buf][kk][tx * 8];
            *(float4*)&b[4] = *(const float4*)&Bs[buf][kk][tx * 8 + 4];
#pragma unroll
            for (int r = 0; r < 8; r++)
#pragma unroll
                for (int c = 0; c < 8; c++)
                    acc[r][c] = fmaf(a[r], b[c], acc[r][c]);
        }
        if (has_next) {
            const int nb = buf ^ 1;
            As[nb][a_kq + 0][a_m] = av.x;
            As[nb][a_kq + 1][a_m] = av.y;
            As[nb][a_kq + 2][a_m] = av.z;
            As[nb][a_kq + 3][a_m] = av.w;
            *(float4*)&Bs[nb][b_k][b_n] = bv;
            __syncthreads();
            buf = nb;
        }
    }

    const int n_base = n0 + tx * 8;
    float bvals[8];
#pragma unroll
    for (int c = 0; c < 8; c++) bvals[c] = bias[n_base + c];

    if (!transhead) {
#pragma unroll
        for (int r = 0; r < 8; r++) {
            int m = m0 + ty * 8 + r;
            float* dst = out + (size_t)m * N + n_base;
            *(float4*)&dst[0] = make_float4(acc[r][0] + bvals[0], acc[r][1] + bvals[1],
                                            acc[r][2] + bvals[2], acc[r][3] + bvals[3]);
            *(float4*)&dst[4] = make_float4(acc[r][4] + bvals[4], acc[r][5] + bvals[5],
                                            acc[r][6] + bvals[6], acc[r][7] + bvals[7]);
        }
    } else {
        const int h = n_base >> 6;       // 8-col group never crosses a head
        const int dkb = n_base & 63;
#pragma unroll
        for (int r = 0; r < 8; r++) {
            int m = m0 + ty * 8 + r;
            int l = m >> 1, bb = m & 1;
            float* dst = out + ((size_t)(h * NB + bb) * L_SEQ + l) * DHEAD + dkb;
            *(float4*)&dst[0] = make_float4(acc[r][0] + bvals[0], acc[r][1] + bvals[1],
                                            acc[r][2] + bvals[2], acc[r][3] + bvals[3]);
            *(float4*)&dst[4] = make_float4(acc[r][4] + bvals[4], acc[r][5] + bvals[5],
                                            acc[r][6] + bvals[6], acc[r][7] + bvals[7]);
        }
    }
}

// Merged Q/K/V projection: gridDim.z = 3 selects which projection.
__global__ void __launch_bounds__(256, 2)
sgemm_qkv_kernel(const float* __restrict__ q, const float* __restrict__ k,
                 const float* __restrict__ v,
                 const float* __restrict__ Wq, const float* __restrict__ Wk,
                 const float* __restrict__ Wv,
                 const float* __restrict__ bq, const float* __restrict__ bk,
                 const float* __restrict__ bv)
{
    const int z = blockIdx.z;
    const float* A = (z == 0) ? q : (z == 1) ? k : v;
    const float* W = (z == 0) ? Wq : (z == 1) ? Wk : Wv;
    const float* bias = (z == 0) ? bq : (z == 1) ? bk : bv;
    float* out = (z == 0) ? g_q : (z == 1) ? g_k : g_v;
    gemm_tile(A, W, bias, out, DM, NH * DHEAD,
              blockIdx.x * 128, blockIdx.y * 128, 1);
}

__global__ void __launch_bounds__(256, 2)
sgemm_fc_kernel(const float* __restrict__ Wfc, const float* __restrict__ bfc)
{
    gemm_tile(g_attnout, Wfc, bfc, g_fc, DM, DM,
              blockIdx.x * 128, blockIdx.y * 128, 0);
}

// =========================================================================
// Banded attention.  Block = (i-block of 128 rows) x (head*batch).
// Phase 1: raw scaled scores -> attn output region (scratch) + row max.
// Phase 2: P = exp(s - m) in smem (64-col halves), O += P @ V, row sums.
// smem ~100KB -> 2 CTAs/SM.
// =========================================================================
#define QS_STRIDE 132
#define VS_STRIDE 68
#define PH_STRIDE 66
#define QS_FLOATS (64 * QS_STRIDE)            // 8448
#define KV_FLOATS 8704                         // max(64*132, 128*68)
#define PS_FLOATS (128 * PH_STRIDE)           // 8448
#define ATTN_SMEM_BYTES ((QS_FLOATS + KV_FLOATS + PS_FLOATS) * 4)

__global__ void __launch_bounds__(256, 2)
attn_kernel(float* __restrict__ attn_raw)
{
    extern __shared__ float smx[];
    float* Qs  = smx;
    float* KVs = smx + QS_FLOATS;
    float* Ps  = smx + QS_FLOATS + KV_FLOATS;

    const int tid = threadIdx.x;
    const int tx = tid & 15, ty = tid >> 4;
    const int i0 = blockIdx.x * 128;
    const int hb = blockIdx.y;

    const float* Qg = g_q + (size_t)hb * L_SEQ * DHEAD;
    const float* Kg = g_k + (size_t)hb * L_SEQ * DHEAD;
    const float* Vg = g_v + (size_t)hb * L_SEQ * DHEAD;
    float* rawbase = attn_raw + (size_t)hb * L_SEQ * L_SEQ;

    // load Q tile transposed: Qs[dk][i]
    {
        const float* src = Qg + (size_t)i0 * DHEAD;
        for (int idx = tid; idx < 128 * 16; idx += 256) {
            int r = idx >> 4, kq = (idx & 15) << 2;
            float4 v = *(const float4*)&src[r * 64 + kq];
            Qs[(kq + 0) * QS_STRIDE + r] = v.x;
            Qs[(kq + 1) * QS_STRIDE + r] = v.y;
            Qs[(kq + 2) * QS_STRIDE + r] = v.z;
            Qs[(kq + 3) * QS_STRIDE + r] = v.w;
        }
    }

    float rm[8];
#pragma unroll
    for (int r = 0; r < 8; r++) rm[r] = -FLT_MAX;

    const int ibase = i0 + ty * 8;

    // ---------------- Phase 1: raw scores + row max ----------------
    for (int cch = 0; cch < 3; cch++) {
        int j0 = i0 + (cch - 1) * 128;
        if (j0 < 0 || j0 >= L_SEQ) continue;
        __syncthreads();
        {
            const float* src = Kg + (size_t)j0 * DHEAD;
            for (int idx = tid; idx < 128 * 16; idx += 256) {
                int r = idx >> 4, kq = (idx & 15) << 2;
                float4 v = *(const float4*)&src[r * 64 + kq];
                KVs[(kq + 0) * QS_STRIDE + r] = v.x;
                KVs[(kq + 1) * QS_STRIDE + r] = v.y;
                KVs[(kq + 2) * QS_STRIDE + r] = v.z;
                KVs[(kq + 3) * QS_STRIDE + r] = v.w;
            }
        }
        __syncthreads();
        float s[8][8];
#pragma unroll
        for (int r = 0; r < 8; r++)
#pragma unroll
            for (int c = 0; c < 8; c++) s[r][c] = 0.f;

        for (int kk = 0; kk < 64; kk++) {
            float a[8], b[8];
            *(float4*)&a[0] = *(const float4*)&Qs[kk * QS_STRIDE + ty * 8];
            *(float4*)&a[4] = *(const float4*)&Qs[kk * QS_STRIDE + ty * 8 + 4];
            *(float4*)&b[0] = *(const float4*)&KVs[kk * QS_STRIDE + tx * 8];
            *(float4*)&b[4] = *(const float4*)&KVs[kk * QS_STRIDE + tx * 8 + 4];
#pragma unroll
            for (int r = 0; r < 8; r++)
#pragma unroll
                for (int c = 0; c < 8; c++)
                    s[r][c] = fmaf(a[r], b[c], s[r][c]);
        }
        const int jbase = j0 + tx * 8;
#pragma unroll
        for (int r = 0; r < 8; r++) {
            int i = ibase + r;
            float* rowp = rawbase + (size_t)i * L_SEQ;
#pragma unroll
            for (int c2 = 0; c2 < 8; c2++) {
                int j = jbase + c2;
                int d = i - j;
                if (d >= -SPAN_W && d <= SPAN_W) {
                    float v = s[r][c2] * 0.125f;
                    rowp[j] = v;
                    rm[r] = fmaxf(rm[r], v);
                }
            }
        }
    }

    // reduce row max across the 16 tx lanes
#pragma unroll
    for (int r = 0; r < 8; r++) {
#pragma unroll
        for (int off = 8; off > 0; off >>= 1)
            rm[r] = fmaxf(rm[r], __shfl_xor_sync(0xffffffffu, rm[r], off, 16));
    }

    // ---------------- Phase 2: P = exp(s-m), O = P @ V, row sums ---------
    float O[8][4];
    float ll[8];
#pragma unroll
    for (int r = 0; r < 8; r++) {
        ll[r] = 0.f;
#pragma unroll
        for (int c = 0; c < 4; c++) O[r][c] = 0.f;
    }

    for (int cch = 0; cch < 3; cch++) {
        int j0 = i0 + (cch - 1) * 128;
        if (j0 < 0 || j0 >= L_SEQ) continue;
        __syncthreads();   // prev chunk's KVs/Ps fully consumed
        {
            const float* src = Vg + (size_t)j0 * DHEAD;
            for (int idx = tid; idx < 128 * 16; idx += 256) {
                int r = idx >> 4, kq = (idx & 15) << 2;
                *(float4*)&KVs[r * VS_STRIDE + kq] = *(const float4*)&src[r * 64 + kq];
            }
        }
        __syncthreads();   // V ready

#pragma unroll
        for (int half = 0; half < 2; half++) {
            if ((tx >> 3) == half) {
                const int txh = tx & 7;
                const int jbase = j0 + tx * 8;
#pragma unroll
                for (int r = 0; r < 8; r++) {
                    int i = ibase + r;
                    const float* rowp = rawbase + (size_t)i * L_SEQ;
                    float* prow = Ps + (size_t)(ty * 8 + r) * PH_STRIDE + txh * 8;
#pragma unroll
                    for (int c2 = 0; c2 < 8; c2++) {
                        int j = jbase + c2;
                        int d = i - j;
                        float p = 0.f;
                        if (d >= -SPAN_W && d <= SPAN_W)
                            p = __expf(rowp[j] - rm[r]);
                        ll[r] += p;
                        prow[c2] = p;
                    }
                }
            }
            __syncthreads();   // Ps half ready
            const int joff = half * 64;
            for (int jj = 0; jj < 64; jj++) {
                float4 v4 = *(const float4*)&KVs[(jj + joff) * VS_STRIDE + tx * 4];
#pragma unroll
                for (int r = 0; r < 8; r++) {
                    float pv = Ps[(size_t)(ty * 8 + r) * PH_STRIDE + jj];
                    O[r][0] = fmaf(pv, v4.x, O[r][0]);
                    O[r][1] = fmaf(pv, v4.y, O[r][1]);
                    O[r][2] = fmaf(pv, v4.z, O[r][2]);
                    O[r][3] = fmaf(pv, v4.w, O[r][3]);
                }
            }
            if (half == 0) __syncthreads();   // half consumed before overwrite
        }
    }

    // reduce row sums across tx lanes
#pragma unroll
    for (int r = 0; r < 8; r++) {
#pragma unroll
        for (int off = 8; off > 0; off >>= 1)
            ll[r] += __shfl_xor_sync(0xffffffffu, ll[r], off, 16);
    }

    const int h = hb >> 1, bb = hb & 1;
#pragma unroll
    for (int r = 0; r < 8; r++) {
        int i = ibase + r;
        float inv = 1.f / ll[r];
        float4 o4 = make_float4(O[r][0] * inv, O[r][1] * inv,
                                O[r][2] * inv, O[r][3] * inv);
        *(float4*)&g_attnout[((size_t)i * NB + bb) * DM + h * DHEAD + tx * 4] = o4;
        if (tx == 0) {
            g_rowm[hb * L_SEQ + i] = rm[r];
            g_rowl[hb * L_SEQ + i] = ll[r];
        }
    }
}

// =========================================================================
// Normalize raw scores -> softmax weights; zero out-of-band (band-only read).
// One block per attention row (hb*L + i), 256 threads x 8 cols.
// =========================================================================
__global__ void __launch_bounds__(256)
attn_norm_kernel(float* __restrict__ attn)
{
    const int row = blockIdx.x;               // hb*L + i
    const int i = row & (L_SEQ - 1);
    const float m = g_rowm[row];
    const float inv = 1.f / g_rowl[row];
    float* p = attn + (size_t)row * L_SEQ;
    const int j0 = threadIdx.x * 8;
    float out[8];
#pragma unroll
    for (int u = 0; u < 8; u++) {
        int j = j0 + u;
        int d = i - j;
        float raw = 0.f;
        bool inband = (d >= -SPAN_W && d <= SPAN_W);
        if (inband) raw = p[j];
        out[u] = inband ? __expf(raw - m) * inv : 0.f;
    }
    *(float4*)&p[j0]     = make_float4(out[0], out[1], out[2], out[3]);
    *(float4*)&p[j0 + 4] = make_float4(out[4], out[5], out[6], out[7]);
}

// =========================================================================
// Residual + LayerNorm.  One block per row (m = l*B+b), 256 threads x 4.
// =========================================================================
__global__ void __launch_bounds__(256)
ln_kernel(const float* __restrict__ query, const float* __restrict__ gamma,
          const float* __restrict__ beta, float* __restrict__ y)
{
    __shared__ float red[16];
    const int row = blockIdx.x;
    const int t = threadIdx.x;

    float4 f = *(const float4*)&g_fc[(size_t)row * DM + t * 4];
    float4 q = *(const float4*)&query[(size_t)row * DM + t * 4];
    float v0 = f.x + q.x, v1 = f.y + q.y, v2 = f.z + q.z, v3 = f.w + q.w;

    float s = v0 + v1 + v2 + v3;
    float s2 = v0 * v0 + v1 * v1 + v2 * v2 + v3 * v3;
#pragma unroll
    for (int off = 16; off > 0; off >>= 1) {
        s  += __shfl_xor_sync(0xffffffffu, s, off);
        s2 += __shfl_xor_sync(0xffffffffu, s2, off);
    }
    const int warp = t >> 5, lane = t & 31;
    if (lane == 0) { red[warp] = s; red[warp + 8] = s2; }
    __syncthreads();
    if (t < 32) {
        float a  = (lane < 8) ? red[lane] : 0.f;
        float b2 = (lane < 8) ? red[lane + 8] : 0.f;
#pragma unroll
        for (int off = 4; off > 0; off >>= 1) {
            a  += __shfl_xor_sync(0xffffffffu, a, off);
            b2 += __shfl_xor_sync(0xffffffffu, b2, off);
        }
        if (lane == 0) { red[0] = a; red[1] = b2; }
    }
    __syncthreads();
    const float mean = red[0] * (1.f / DM);
    const float var  = red[1] * (1.f / DM) - mean * mean;
    const float rstd = rsqrtf(var + 1e-5f);

    float4 g  = *(const float4*)&gamma[t * 4];
    float4 be = *(const float4*)&beta[t * 4];
    float4 o;
    o.x = (v0 - mean) * rstd * g.x + be.x;
    o.y = (v1 - mean) * rstd * g.y + be.y;
    o.z = (v2 - mean) * rstd * g.z + be.z;
    o.w = (v3 - mean) * rstd * g.w + be.w;
    *(float4*)&y[(size_t)row * DM + t * 4] = o;
}

// =========================================================================
extern "C" void kernel_launch(void* const* d_in, const int* in_sizes, int n_in,
                              void* d_out, int out_size)
{
    const float* query = (const float*)d_in[0];
    const float* key   = (const float*)d_in[1];
    const float* value = (const float*)d_in[2];
    const float* Wq    = (const float*)d_in[3];
    const float* bq    = (const float*)d_in[4];
    const float* Wk    = (const float*)d_in[5];
    const float* bk    = (const float*)d_in[6];
    const float* Wv    = (const float*)d_in[7];
    const float* bv    = (const float*)d_in[8];
    const float* Wfc   = (const float*)d_in[9];
    const float* bfc   = (const float*)d_in[10];
    const float* gamma = (const float*)d_in[11];
    const float* beta  = (const float*)d_in[12];

    float* y_out = (float*)d_out;
    float* attn_out = y_out + (size_t)L_SEQ * NB * DM;

    cudaFuncSetAttribute(attn_kernel,
                         cudaFuncAttributeMaxDynamicSharedMemorySize,
                         ATTN_SMEM_BYTES);

    dim3 gqkv(MROWS / 128, DM / 128, 3);
    sgemm_qkv_kernel<<<gqkv, 256>>>(query, key, value, Wq, Wk, Wv, bq, bk, bv);

    attn_kernel<<<dim3(L_SEQ / 128, HB), 256, ATTN_SMEM_BYTES>>>(attn_out);

    sgemm_fc_kernel<<<dim3(MROWS / 128, DM / 128), 256>>>(Wfc, bfc);

    ln_kernel<<<MROWS, 256>>>(query, gamma, beta, y_out);

    attn_norm_kernel<<<HB * L_SEQ, 256>>>(attn_out);
}